// round 2
// baseline (speedup 1.0000x reference)
#include <cuda_runtime.h>
#include <math.h>

// Problem constants (B=8192, B_pos=8192, D=1024, T=0.1)
#define B_N 8192
#define D_N 1024
#define KINV_T 10.0f

// Scratch (allocation-free rule -> __device__ globals)
static __device__ float g_W[(size_t)B_N * B_N];      // 256 MB weight/score matrix (reused for both passes)
static __device__ float g_attr[(size_t)B_N * D_N];   // 32 MB
static __device__ float g_rep[(size_t)B_N * D_N];    // 32 MB
static __device__ float g_gn[B_N];
static __device__ float g_pn[B_N];
static __device__ float g_part[B_N * 4];

// ---------------- reductions ----------------

__device__ __forceinline__ float warpSum(float v) {
#pragma unroll
    for (int o = 16; o > 0; o >>= 1) v += __shfl_xor_sync(0xffffffffu, v, o);
    return v;
}
__device__ __forceinline__ float warpMax(float v) {
#pragma unroll
    for (int o = 16; o > 0; o >>= 1) v = fmaxf(v, __shfl_xor_sync(0xffffffffu, v, o));
    return v;
}

__device__ float blockSum(float v) {
    __shared__ float s[33];
    int lane = threadIdx.x & 31, w = threadIdx.x >> 5;
    __syncthreads();                 // protect s[] reuse across successive calls
    v = warpSum(v);
    if (lane == 0) s[w] = v;
    __syncthreads();
    if (w == 0) {
        float t = (threadIdx.x < (blockDim.x >> 5)) ? s[threadIdx.x] : 0.f;
        t = warpSum(t);
        if (lane == 0) s[32] = t;
    }
    __syncthreads();
    return s[32];
}

__device__ float blockMax(float v) {
    __shared__ float s[33];
    int lane = threadIdx.x & 31, w = threadIdx.x >> 5;
    __syncthreads();
    v = warpMax(v);
    if (lane == 0) s[w] = v;
    __syncthreads();
    if (w == 0) {
        float t = (threadIdx.x < (blockDim.x >> 5)) ? s[threadIdx.x] : -INFINITY;
        t = warpMax(t);
        if (lane == 0) s[32] = t;
    }
    __syncthreads();
    return s[32];
}

// ---------------- K0: row squared-norms ----------------

__global__ __launch_bounds__(256)
void norms_kernel(const float* __restrict__ gen, const float* __restrict__ pos) {
    int row = blockIdx.x;
    const float* src;
    float* dst;
    if (row < B_N) { src = gen + (size_t)row * D_N; dst = &g_gn[row]; }
    else           { src = pos + (size_t)(row - B_N) * D_N; dst = &g_pn[row - B_N]; }
    float s = 0.f;
    for (int c = threadIdx.x * 4; c < D_N; c += blockDim.x * 4) {
        float4 v = *(const float4*)(src + c);
        s += v.x * v.x + v.y * v.y + v.z * v.z + v.w * v.w;
    }
    s = blockSum(s);
    if (threadIdx.x == 0) *dst = s;
}

// ---------------- K1: score GEMM (NT): g_W[i][j] = -sqrt(max(|a_i|^2+|b_j|^2-2 a_i.b_j,0))/T ----

__global__ __launch_bounds__(256)
void score_gemm(const float* __restrict__ A, const float* __restrict__ Bm, int b_is_gen) {
    __shared__ float As[16][128];   // As[k][m]
    __shared__ float Bs[16][128];   // Bs[k][n]
    const int tx = threadIdx.x, ty = threadIdx.y;
    const int tid = ty * 16 + tx;
    const int m0 = blockIdx.y * 128, n0 = blockIdx.x * 128;

    float acc[8][8];
#pragma unroll
    for (int i = 0; i < 8; i++)
#pragma unroll
        for (int j = 0; j < 8; j++) acc[i][j] = 0.f;

    for (int kt = 0; kt < D_N; kt += 16) {
#pragma unroll
        for (int l = 0; l < 2; l++) {
            int f = tid + l * 256;
            int r = f >> 2, c4 = (f & 3) * 4;
            float4 va = *(const float4*)(A + (size_t)(m0 + r) * D_N + kt + c4);
            As[c4 + 0][r] = va.x; As[c4 + 1][r] = va.y; As[c4 + 2][r] = va.z; As[c4 + 3][r] = va.w;
            float4 vb = *(const float4*)(Bm + (size_t)(n0 + r) * D_N + kt + c4);
            Bs[c4 + 0][r] = vb.x; Bs[c4 + 1][r] = vb.y; Bs[c4 + 2][r] = vb.z; Bs[c4 + 3][r] = vb.w;
        }
        __syncthreads();
#pragma unroll
        for (int k = 0; k < 16; k++) {
            float4 a0 = *(const float4*)&As[k][ty * 8];
            float4 a1 = *(const float4*)&As[k][ty * 8 + 4];
            float4 b0 = *(const float4*)&Bs[k][tx * 8];
            float4 b1 = *(const float4*)&Bs[k][tx * 8 + 4];
            float a[8] = {a0.x, a0.y, a0.z, a0.w, a1.x, a1.y, a1.z, a1.w};
            float b[8] = {b0.x, b0.y, b0.z, b0.w, b1.x, b1.y, b1.z, b1.w};
#pragma unroll
            for (int i = 0; i < 8; i++)
#pragma unroll
                for (int j = 0; j < 8; j++) acc[i][j] = fmaf(a[i], b[j], acc[i][j]);
        }
        __syncthreads();
    }

    const float* bn = b_is_gen ? g_gn : g_pn;
    float an[8], bnv[8];
#pragma unroll
    for (int i = 0; i < 8; i++) an[i] = g_gn[m0 + ty * 8 + i];
#pragma unroll
    for (int j = 0; j < 8; j++) bnv[j] = bn[n0 + tx * 8 + j];

#pragma unroll
    for (int i = 0; i < 8; i++) {
        float o[8];
#pragma unroll
        for (int j = 0; j < 8; j++) {
            float d2 = fmaxf(an[i] + bnv[j] - 2.f * acc[i][j], 0.f);
            o[j] = -sqrtf(d2) * KINV_T;
        }
        size_t base = (size_t)(m0 + ty * 8 + i) * B_N + n0 + tx * 8;
        *(float4*)&g_W[base]     = make_float4(o[0], o[1], o[2], o[3]);
        *(float4*)&g_W[base + 4] = make_float4(o[4], o[5], o[6], o[7]);
    }
}

// ---------------- K2: row softmax in-place on g_W (optional diagonal mask) ----------------

__global__ __launch_bounds__(256)
void softmax_rows(int mask_diag) {
    __shared__ float sm[B_N];   // 32 KB: whole row cached in smem
    int row = blockIdx.x;
    float* Wrow = g_W + (size_t)row * B_N;
    float mx = -INFINITY;
    for (int j = threadIdx.x; j < B_N; j += blockDim.x) {
        float v = Wrow[j];
        if (mask_diag && j == row) v = -INFINITY;   // diag distance ~0 would dominate; must mask
        sm[j] = v;
        mx = fmaxf(mx, v);
    }
    mx = blockMax(mx);
    float sum = 0.f;
    for (int j = threadIdx.x; j < B_N; j += blockDim.x) {
        float e = expf(sm[j] - mx);                 // exp(-inf) = 0 handles the mask
        sm[j] = e;
        sum += e;
    }
    sum = blockSum(sum);
    float inv = 1.f / sum;
    for (int j = threadIdx.x; j < B_N; j += blockDim.x)
        Wrow[j] = sm[j] * inv;
}

// ---------------- K3: weighted-average GEMM (NN): out = g_W @ Bm - sub ----------------

__global__ __launch_bounds__(256)
void wavg_gemm(const float* __restrict__ Bm, const float* __restrict__ sub, int to_rep) {
    __shared__ float As[16][128];   // As[k][m]  (from g_W)
    __shared__ float Bs[16][128];   // Bs[k][n]
    const int tx = threadIdx.x, ty = threadIdx.y;
    const int tid = ty * 16 + tx;
    const int m0 = blockIdx.y * 128, n0 = blockIdx.x * 128;

    float acc[8][8];
#pragma unroll
    for (int i = 0; i < 8; i++)
#pragma unroll
        for (int j = 0; j < 8; j++) acc[i][j] = 0.f;

    for (int kt = 0; kt < B_N; kt += 16) {
#pragma unroll
        for (int l = 0; l < 2; l++) {
            int f = tid + l * 256;
            int r = f >> 2, c4 = (f & 3) * 4;
            float4 va = *(const float4*)(g_W + (size_t)(m0 + r) * B_N + kt + c4);
            As[c4 + 0][r] = va.x; As[c4 + 1][r] = va.y; As[c4 + 2][r] = va.z; As[c4 + 3][r] = va.w;
            int kk = f >> 5, n4 = (f & 31) * 4;
            float4 vb = *(const float4*)(Bm + (size_t)(kt + kk) * D_N + n0 + n4);
            *(float4*)&Bs[kk][n4] = vb;
        }
        __syncthreads();
#pragma unroll
        for (int k = 0; k < 16; k++) {
            float4 a0 = *(const float4*)&As[k][ty * 8];
            float4 a1 = *(const float4*)&As[k][ty * 8 + 4];
            float4 b0 = *(const float4*)&Bs[k][tx * 8];
            float4 b1 = *(const float4*)&Bs[k][tx * 8 + 4];
            float a[8] = {a0.x, a0.y, a0.z, a0.w, a1.x, a1.y, a1.z, a1.w};
            float b[8] = {b0.x, b0.y, b0.z, b0.w, b1.x, b1.y, b1.z, b1.w};
#pragma unroll
            for (int i = 0; i < 8; i++)
#pragma unroll
                for (int j = 0; j < 8; j++) acc[i][j] = fmaf(a[i], b[j], acc[i][j]);
        }
        __syncthreads();
    }

    float* out = to_rep ? g_rep : g_attr;
#pragma unroll
    for (int i = 0; i < 8; i++) {
        size_t base = (size_t)(m0 + ty * 8 + i) * D_N + n0 + tx * 8;
        float4 s0 = *(const float4*)(sub + base);
        float4 s1 = *(const float4*)(sub + base + 4);
        *(float4*)&out[base]     = make_float4(acc[i][0] - s0.x, acc[i][1] - s0.y,
                                               acc[i][2] - s0.z, acc[i][3] - s0.w);
        *(float4*)&out[base + 4] = make_float4(acc[i][4] - s1.x, acc[i][5] - s1.y,
                                               acc[i][6] - s1.z, acc[i][7] - s1.w);
    }
}

// ---------------- K4: per-row norms / loss partials ----------------

__global__ __launch_bounds__(256)
void row_reduce() {
    int row = blockIdx.x;
    const float* a = g_attr + (size_t)row * D_N;
    const float* r = g_rep + (size_t)row * D_N;
    float sa = 0.f, sr = 0.f, sd = 0.f;
    for (int c = threadIdx.x * 4; c < D_N; c += blockDim.x * 4) {
        float4 av = *(const float4*)(a + c);
        float4 rv = *(const float4*)(r + c);
        float dx = av.x - rv.x, dy = av.y - rv.y, dz = av.z - rv.z, dw = av.w - rv.w;
        sa += av.x * av.x + av.y * av.y + av.z * av.z + av.w * av.w;
        sr += rv.x * rv.x + rv.y * rv.y + rv.z * rv.z + rv.w * rv.w;
        sd += dx * dx + dy * dy + dz * dz + dw * dw;
    }
    sa = blockSum(sa);
    sr = blockSum(sr);
    sd = blockSum(sd);
    if (threadIdx.x == 0) {
        g_part[row * 4 + 0] = sd;          // sum drift^2 (loss numerator)
        g_part[row * 4 + 1] = sqrtf(sd);   // ||drift||
        g_part[row * 4 + 2] = sqrtf(sa);   // ||attraction||
        g_part[row * 4 + 3] = sqrtf(sr);   // ||repulsion||
    }
}

// ---------------- K5: final 4-scalar output ----------------

__global__ __launch_bounds__(256)
void final_reduce(float* __restrict__ out) {
    float s0 = 0.f, s1 = 0.f, s2 = 0.f, s3 = 0.f;
    for (int i = threadIdx.x; i < B_N; i += blockDim.x) {
        s0 += g_part[i * 4 + 0];
        s1 += g_part[i * 4 + 1];
        s2 += g_part[i * 4 + 2];
        s3 += g_part[i * 4 + 3];
    }
    s0 = blockSum(s0);
    s1 = blockSum(s1);
    s2 = blockSum(s2);
    s3 = blockSum(s3);
    if (threadIdx.x == 0) {
        out[0] = s0 / ((float)B_N * (float)D_N);   // loss = mean(drift^2)
        out[1] = s1 / (float)B_N;                  // drift_norm
        out[2] = s2 / (float)B_N;                  // attraction_norm
        out[3] = s3 / (float)B_N;                  // repulsion_norm
    }
}

// ---------------- launch ----------------

extern "C" void kernel_launch(void* const* d_in, const int* in_sizes, int n_in,
                              void* d_out, int out_size) {
    const float* gen = (const float*)d_in[0];
    const float* pos = (const float*)d_in[1];
    float* out = (float*)d_out;
    dim3 blk(16, 16);

    norms_kernel<<<2 * B_N, 256>>>(gen, pos);

    // Attraction pass: scores(gen,pos) -> softmax -> W@pos - gen
    score_gemm<<<dim3(B_N / 128, B_N / 128), blk>>>(gen, pos, 0);
    softmax_rows<<<B_N, 256>>>(0);
    wavg_gemm<<<dim3(D_N / 128, B_N / 128), blk>>>(pos, gen, 0);

    // Repulsion pass: scores(gen,gen) with diag mask -> softmax -> W@gen - gen
    score_gemm<<<dim3(B_N / 128, B_N / 128), blk>>>(gen, gen, 1);
    softmax_rows<<<B_N, 256>>>(1);
    wavg_gemm<<<dim3(D_N / 128, B_N / 128), blk>>>(gen, gen, 1);

    row_reduce<<<B_N, 256>>>();
    final_reduce<<<1, 256>>>(out);
}

// round 6
// speedup vs baseline: 1.4458x; 1.4458x over previous
#include <cuda_runtime.h>
#include <cuda_fp16.h>
#include <mma.h>
#include <math.h>
#include <stdint.h>

using namespace nvcuda;

// Problem constants (B=8192, B_pos=8192, D=1024, T=0.1)
#define B_N 8192
#define D_N 1024

// ---------------- scratch (__device__ globals; no allocs) ----------------
static __device__ __align__(256) float  g_S[(size_t)B_N * B_N];      // 256 MB scores -> softmax weights (in-place, fp32)
static __device__ __align__(256) __half g_genH[(size_t)B_N * D_N];   // 16 MB fp16 hi plane of gen
static __device__ __align__(256) __half g_genL[(size_t)B_N * D_N];   // 16 MB fp16 lo plane of gen
static __device__ __align__(256) __half g_posH[(size_t)B_N * D_N];   // 16 MB
static __device__ __align__(256) __half g_posL[(size_t)B_N * D_N];   // 16 MB
static __device__ __align__(256) float g_attr[(size_t)B_N * D_N];    // 32 MB
static __device__ __align__(256) float g_rep[(size_t)B_N * D_N];     // 32 MB
static __device__ float g_gn[B_N];
static __device__ float g_pn[B_N];
static __device__ float g_part[B_N * 4];

// ---------------- reductions (proven) ----------------
__device__ __forceinline__ float warpSum(float v) {
#pragma unroll
    for (int o = 16; o > 0; o >>= 1) v += __shfl_xor_sync(0xffffffffu, v, o);
    return v;
}
__device__ __forceinline__ float warpMax(float v) {
#pragma unroll
    for (int o = 16; o > 0; o >>= 1) v = fmaxf(v, __shfl_xor_sync(0xffffffffu, v, o));
    return v;
}
__device__ float blockSum(float v) {
    __shared__ float s[33];
    int lane = threadIdx.x & 31, w = threadIdx.x >> 5;
    __syncthreads();
    v = warpSum(v);
    if (lane == 0) s[w] = v;
    __syncthreads();
    if (w == 0) {
        float t = (threadIdx.x < (blockDim.x >> 5)) ? s[threadIdx.x] : 0.f;
        t = warpSum(t);
        if (lane == 0) s[32] = t;
    }
    __syncthreads();
    return s[32];
}
__device__ float blockMax(float v) {
    __shared__ float s[33];
    int lane = threadIdx.x & 31, w = threadIdx.x >> 5;
    __syncthreads();
    v = warpMax(v);
    if (lane == 0) s[w] = v;
    __syncthreads();
    if (w == 0) {
        float t = (threadIdx.x < (blockDim.x >> 5)) ? s[threadIdx.x] : -INFINITY;
        t = warpMax(t);
        if (lane == 0) s[32] = t;
    }
    __syncthreads();
    return s[32];
}

// ---------------- K0: row squared norms (proven) ----------------
__global__ __launch_bounds__(256)
void norms_kernel(const float* __restrict__ gen, const float* __restrict__ pos) {
    int row = blockIdx.x;
    const float* src; float* dst;
    if (row < B_N) { src = gen + (size_t)row * D_N; dst = &g_gn[row]; }
    else           { src = pos + (size_t)(row - B_N) * D_N; dst = &g_pn[row - B_N]; }
    float s = 0.f;
    for (int c = threadIdx.x * 4; c < D_N; c += blockDim.x * 4) {
        float4 v = *(const float4*)(src + c);
        s += v.x * v.x + v.y * v.y + v.z * v.z + v.w * v.w;
    }
    s = blockSum(s);
    if (threadIdx.x == 0) *dst = s;
}

// ---------------- K1: fp16 hi/lo plane split ----------------
__global__ __launch_bounds__(256)
void split16(const float* __restrict__ gen, const float* __restrict__ pos) {
    const size_t total = (size_t)B_N * D_N;
    for (size_t idx = (size_t)blockIdx.x * blockDim.x + threadIdx.x; idx < total;
         idx += (size_t)gridDim.x * blockDim.x) {
        float x = gen[idx];
        __half h = __float2half(x);
        g_genH[idx] = h;
        g_genL[idx] = __float2half(x - __half2float(h));
        float y = pos[idx];
        __half hp = __float2half(y);
        g_posH[idx] = hp;
        g_posL[idx] = __float2half(y - __half2float(hp));
    }
}

// ---------------- K2: score GEMM via WMMA (compiler-managed fragments) ----------------
// S[i][j] = -10*sqrt(max(gn_i + bn_j - 2*dot3(gen_i, b_j), 0))
// dot3 accumulated over 3 plane-segments: (H,H), (H,L), (L,H)  -> ~fp32-quality dot.
#define LDS 72                 // padded smem stride in halves
#define TILE_H (128 * LDS)     // 9216 halves per tile

__global__ __launch_bounds__(256)
void score_wmma(int b_is_gen) {
    __shared__ __align__(32) __half sh[2 * TILE_H];   // 36,864 B
    __half* shA = sh;
    __half* shB = sh + TILE_H;

    const int tid = threadIdx.x, lane = tid & 31, wid = tid >> 5;
    const int wm = (wid & 3) * 32, wn = (wid >> 2) * 64;   // warp tile 32x64
    const int m0 = blockIdx.y * 128, n0 = blockIdx.x * 128;

    const __half* segA[3] = { g_genH, g_genH, g_genL };
    const __half* segB[3];
    if (b_is_gen) { segB[0] = g_genH; segB[1] = g_genL; segB[2] = g_genH; }
    else          { segB[0] = g_posH; segB[1] = g_posL; segB[2] = g_posH; }

    wmma::fragment<wmma::accumulator, 16, 16, 16, float> cfr[2][4];
#pragma unroll
    for (int i = 0; i < 2; i++)
#pragma unroll
        for (int j = 0; j < 4; j++) wmma::fill_fragment(cfr[i][j], 0.f);

    for (int seg = 0; seg < 3; seg++) {
        const __half* A = segA[seg];
        const __half* B = segB[seg];
        for (int t = 0; t < D_N / 64; t++) {
            __syncthreads();   // WAR: previous tile fully consumed
#pragma unroll
            for (int i = 0; i < 4; i++) {
                int f = i * 256 + tid, r = f >> 3, cc = f & 7;
                *(uint4*)(shA + r * LDS + cc * 8) =
                    *(const uint4*)(A + (size_t)(m0 + r) * D_N + t * 64 + cc * 8);
                *(uint4*)(shB + r * LDS + cc * 8) =
                    *(const uint4*)(B + (size_t)(n0 + r) * D_N + t * 64 + cc * 8);
            }
            __syncthreads();
#pragma unroll
            for (int ks = 0; ks < 4; ks++) {
                wmma::fragment<wmma::matrix_a, 16, 16, 16, __half, wmma::row_major> afr[2];
                wmma::fragment<wmma::matrix_b, 16, 16, 16, __half, wmma::col_major> bfr[4];
#pragma unroll
                for (int i = 0; i < 2; i++)
                    wmma::load_matrix_sync(afr[i], shA + (wm + i * 16) * LDS + ks * 16, LDS);
#pragma unroll
                for (int j = 0; j < 4; j++)
                    wmma::load_matrix_sync(bfr[j], shB + (wn + j * 16) * LDS + ks * 16, LDS);
#pragma unroll
                for (int i = 0; i < 2; i++)
#pragma unroll
                    for (int j = 0; j < 4; j++)
                        wmma::mma_sync(cfr[i][j], afr[i], bfr[j], cfr[i][j]);
            }
        }
    }

    // epilogue: stage each 16x16 accum tile through smem, transform, write
    __syncthreads();
    float* patch = ((float*)sh) + wid * 256;   // disjoint per warp
    const float* bnp = b_is_gen ? g_gn : g_pn;
#pragma unroll
    for (int i = 0; i < 2; i++) {
#pragma unroll
        for (int j = 0; j < 4; j++) {
            wmma::store_matrix_sync(patch, cfr[i][j], 16, wmma::mem_row_major);
            __syncwarp();
            const int pr = lane >> 1, pc = (lane & 1) * 8;
            const int row = m0 + wm + i * 16 + pr;
            const int colb = n0 + wn + j * 16 + pc;
            const float an = g_gn[row];
            float4 bn0 = *(const float4*)(bnp + colb);
            float4 bn1 = *(const float4*)(bnp + colb + 4);
            const float* p = patch + pr * 16 + pc;
            float o[8];
            float bns[8] = {bn0.x, bn0.y, bn0.z, bn0.w, bn1.x, bn1.y, bn1.z, bn1.w};
#pragma unroll
            for (int e = 0; e < 8; e++) {
                float d2 = fmaxf(an + bns[e] - 2.f * p[e], 0.f);
                o[e] = -10.f * sqrtf(d2);
            }
            float* dst = g_S + (size_t)row * B_N + colb;
            *(float4*)dst       = make_float4(o[0], o[1], o[2], o[3]);
            *(float4*)(dst + 4) = make_float4(o[4], o[5], o[6], o[7]);
            __syncwarp();
        }
    }
}

// ---------------- K3: row softmax in-place on g_S (proven R2) ----------------
__global__ __launch_bounds__(256)
void softmax_rows(int mask_diag) {
    __shared__ float sm[B_N];
    int row = blockIdx.x;
    float* Wrow = g_S + (size_t)row * B_N;
    float mx = -INFINITY;
    for (int j = threadIdx.x; j < B_N; j += blockDim.x) {
        float v = Wrow[j];
        if (mask_diag && j == row) v = -INFINITY;
        sm[j] = v;
        mx = fmaxf(mx, v);
    }
    mx = blockMax(mx);
    float sum = 0.f;
    for (int j = threadIdx.x; j < B_N; j += blockDim.x) {
        float e = expf(sm[j] - mx);
        sm[j] = e;
        sum += e;
    }
    sum = blockSum(sum);
    float inv = 1.f / sum;
    for (int j = threadIdx.x; j < B_N; j += blockDim.x)
        Wrow[j] = sm[j] * inv;
}

// ---------------- K4: wavg GEMM (proven R2 SIMT fp32): out = g_S @ Bm - sub ----------------
__global__ __launch_bounds__(256)
void wavg_gemm(const float* __restrict__ Bm, const float* __restrict__ sub, int to_rep) {
    __shared__ float As[16][128];
    __shared__ float Bs[16][128];
    const int tx = threadIdx.x, ty = threadIdx.y;
    const int tid = ty * 16 + tx;
    const int m0 = blockIdx.y * 128, n0 = blockIdx.x * 128;

    float acc[8][8];
#pragma unroll
    for (int i = 0; i < 8; i++)
#pragma unroll
        for (int j = 0; j < 8; j++) acc[i][j] = 0.f;

    for (int kt = 0; kt < B_N; kt += 16) {
#pragma unroll
        for (int l = 0; l < 2; l++) {
            int f = tid + l * 256;
            int r = f >> 2, c4 = (f & 3) * 4;
            float4 va = *(const float4*)(g_S + (size_t)(m0 + r) * B_N + kt + c4);
            As[c4 + 0][r] = va.x; As[c4 + 1][r] = va.y; As[c4 + 2][r] = va.z; As[c4 + 3][r] = va.w;
            int kk = f >> 5, n4 = (f & 31) * 4;
            float4 vb = *(const float4*)(Bm + (size_t)(kt + kk) * D_N + n0 + n4);
            *(float4*)&Bs[kk][n4] = vb;
        }
        __syncthreads();
#pragma unroll
        for (int k = 0; k < 16; k++) {
            float4 a0 = *(const float4*)&As[k][ty * 8];
            float4 a1 = *(const float4*)&As[k][ty * 8 + 4];
            float4 b0 = *(const float4*)&Bs[k][tx * 8];
            float4 b1 = *(const float4*)&Bs[k][tx * 8 + 4];
            float a[8] = {a0.x, a0.y, a0.z, a0.w, a1.x, a1.y, a1.z, a1.w};
            float b[8] = {b0.x, b0.y, b0.z, b0.w, b1.x, b1.y, b1.z, b1.w};
#pragma unroll
            for (int i = 0; i < 8; i++)
#pragma unroll
                for (int j = 0; j < 8; j++) acc[i][j] = fmaf(a[i], b[j], acc[i][j]);
        }
        __syncthreads();
    }

    float* out = to_rep ? g_rep : g_attr;
#pragma unroll
    for (int i = 0; i < 8; i++) {
        size_t base = (size_t)(m0 + ty * 8 + i) * D_N + n0 + tx * 8;
        float4 s0 = *(const float4*)(sub + base);
        float4 s1 = *(const float4*)(sub + base + 4);
        *(float4*)&out[base]     = make_float4(acc[i][0] - s0.x, acc[i][1] - s0.y,
                                               acc[i][2] - s0.z, acc[i][3] - s0.w);
        *(float4*)&out[base + 4] = make_float4(acc[i][4] - s1.x, acc[i][5] - s1.y,
                                               acc[i][6] - s1.z, acc[i][7] - s1.w);
    }
}

// ---------------- K5/K6: final reductions (proven) ----------------
__global__ __launch_bounds__(256)
void row_reduce() {
    int row = blockIdx.x;
    const float* a = g_attr + (size_t)row * D_N;
    const float* r = g_rep + (size_t)row * D_N;
    float sa = 0.f, sr = 0.f, sd = 0.f;
    for (int c = threadIdx.x * 4; c < D_N; c += blockDim.x * 4) {
        float4 av = *(const float4*)(a + c);
        float4 rv = *(const float4*)(r + c);
        float dx = av.x - rv.x, dy = av.y - rv.y, dz = av.z - rv.z, dw = av.w - rv.w;
        sa += av.x * av.x + av.y * av.y + av.z * av.z + av.w * av.w;
        sr += rv.x * rv.x + rv.y * rv.y + rv.z * rv.z + rv.w * rv.w;
        sd += dx * dx + dy * dy + dz * dz + dw * dw;
    }
    sa = blockSum(sa); sr = blockSum(sr); sd = blockSum(sd);
    if (threadIdx.x == 0) {
        g_part[row * 4 + 0] = sd;
        g_part[row * 4 + 1] = sqrtf(sd);
        g_part[row * 4 + 2] = sqrtf(sa);
        g_part[row * 4 + 3] = sqrtf(sr);
    }
}

__global__ __launch_bounds__(256)
void final_reduce(float* __restrict__ out) {
    float s0 = 0.f, s1 = 0.f, s2 = 0.f, s3 = 0.f;
    for (int i = threadIdx.x; i < B_N; i += blockDim.x) {
        s0 += g_part[i * 4 + 0]; s1 += g_part[i * 4 + 1];
        s2 += g_part[i * 4 + 2]; s3 += g_part[i * 4 + 3];
    }
    s0 = blockSum(s0); s1 = blockSum(s1); s2 = blockSum(s2); s3 = blockSum(s3);
    if (threadIdx.x == 0) {
        out[0] = s0 / ((float)B_N * (float)D_N);
        out[1] = s1 / (float)B_N;
        out[2] = s2 / (float)B_N;
        out[3] = s3 / (float)B_N;
    }
}

// ---------------- launch ----------------
extern "C" void kernel_launch(void* const* d_in, const int* in_sizes, int n_in,
                              void* d_out, int out_size) {
    const float* gen = (const float*)d_in[0];
    const float* pos = (const float*)d_in[1];
    float* out = (float*)d_out;
    dim3 blk(16, 16);

    norms_kernel<<<2 * B_N, 256>>>(gen, pos);
    split16<<<4096, 256>>>(gen, pos);

    // Attraction: scores(gen,pos) -> softmax -> W@pos - gen
    score_wmma<<<dim3(64, 64), 256>>>(0);
    softmax_rows<<<B_N, 256>>>(0);
    wavg_gemm<<<dim3(D_N / 128, B_N / 128), blk>>>(pos, gen, 0);

    // Repulsion: scores(gen,gen) diag-masked -> softmax -> W@gen - gen
    score_wmma<<<dim3(64, 64), 256>>>(1);
    softmax_rows<<<B_N, 256>>>(1);
    wavg_gemm<<<dim3(D_N / 128, B_N / 128), blk>>>(gen, gen, 1);

    row_reduce<<<B_N, 256>>>();
    final_reduce<<<1, 256>>>(out);
}